// round 16
// baseline (speedup 1.0000x reference)
#include <cuda_runtime.h>
#include <cuda_bf16.h>
#include <cstdint>

// ---------------- problem constants ----------------
#define NNODES 10000
#define NEDGES 160000
#define F_IN   2000
#define HID    128

// ---------------- device scratch (no cudaMalloc allowed) ----------------
__device__ float g_wr[2000 * 768 + 128 * 128 + 128 * 512 + 128 * 64 + 2000 * 64 + 192 * 64];
__device__ float g_h1[NNODES * 768];      // x @ W_gat1  [N,6,128]
__device__ float g_as1[NNODES * 6];
__device__ float g_ad1[NNODES * 6];
__device__ float g_x1gat[NNODES * 128];
__device__ float g_y1[NNODES * 128];      // x1_gat @ W_gcn1
__device__ float g_cat[NNODES * 192];     // [x1_gcn | x2_gcn]
__device__ float g_h2[NNODES * 512];      // x1_gcn @ W_gat2 [N,4,128]
__device__ float g_as2[NNODES * 4];
__device__ float g_ad2[NNODES * 4];
__device__ float g_x2gat[NNODES * 128];
__device__ float g_y2[NNODES * 64];       // x2_gat @ W_gcn2
__device__ float g_skip[NNODES * 64];
__device__ float g_fused[NNODES * 64];
__device__ int   g_deg[NNODES];
__device__ int   g_cursor[NNODES];
__device__ int   g_rowptr[NNODES + 1];
__device__ int   g_col[NEDGES];
__device__ float g_dinv[NNODES];

// weight offsets inside g_wr
#define WOFF_GAT1 0
#define WOFF_GCN1 (WOFF_GAT1 + 2000 * 768)
#define WOFF_GAT2 (WOFF_GCN1 + 128 * 128)
#define WOFF_GCN2 (WOFF_GAT2 + 128 * 512)
#define WOFF_SKIP (WOFF_GCN2 + 128 * 64)
#define WOFF_FUSE (WOFF_SKIP + 2000 * 64)

__device__ __forceinline__ uint32_t f2tf32(float x) {
    uint32_t r;
    asm("cvt.rna.tf32.f32 %0, %1;" : "=r"(r) : "f"(x));
    return r;
}
__device__ __forceinline__ float rnd_tf32f(float x) {
    return __uint_as_float(f2tf32(x));
}

// fused rounding of all six GEMM weights in one launch
__global__ void round_weights_kernel(
    const float* __restrict__ w0, float* __restrict__ o0, int n0,
    const float* __restrict__ w1, float* __restrict__ o1, int n1,
    const float* __restrict__ w2, float* __restrict__ o2, int n2,
    const float* __restrict__ w3, float* __restrict__ o3, int n3,
    const float* __restrict__ w4, float* __restrict__ o4, int n4,
    const float* __restrict__ w5, float* __restrict__ o5, int n5)
{
    int i = blockIdx.x * blockDim.x + threadIdx.x;
    auto doseg = [&](const float* w, float* o, int n) {
        if (i < n) {
            float4 v = ((const float4*)w)[i];
            v.x = rnd_tf32f(v.x); v.y = rnd_tf32f(v.y);
            v.z = rnd_tf32f(v.z); v.w = rnd_tf32f(v.w);
            ((float4*)o)[i] = v;
        }
    };
    doseg(w0, o0, n0); doseg(w1, o1, n1); doseg(w2, o2, n2);
    doseg(w3, o3, n3); doseg(w4, o4, n4); doseg(w5, o5, n5);
}

// ---------------- graph build ----------------
__global__ void zero_kernel(int n) {
    int i = blockIdx.x * blockDim.x + threadIdx.x;
    if (i < n) { g_deg[i] = 0; g_cursor[i] = 0; }
}

__global__ void deg_kernel(const int* __restrict__ ei, int E) {
    int e = blockIdx.x * blockDim.x + threadIdx.x;
    if (e < E) atomicAdd(&g_deg[ei[E + e]], 1);
}

// two-level warp-shuffle scan
__global__ void scan_kernel(int n) {
    __shared__ int warpsum[32];
    const int tid = threadIdx.x;
    const int lane = tid & 31, wrp = tid >> 5;
    constexpr int CH = 10;
    const int base = tid * CH;
    int loc[CH];
    int mysum = 0;
#pragma unroll
    for (int k = 0; k < CH; k++) {
        int i = base + k;
        int v = (i < n) ? g_deg[i] : 0;
        loc[k] = mysum;
        mysum += v;
    }
    int incl = mysum;
#pragma unroll
    for (int off = 1; off < 32; off <<= 1) {
        int t = __shfl_up_sync(0xFFFFFFFFu, incl, off);
        if (lane >= off) incl += t;
    }
    if (lane == 31) warpsum[wrp] = incl;
    __syncthreads();
    if (wrp == 0) {
        int v = warpsum[lane];
#pragma unroll
        for (int off = 1; off < 32; off <<= 1) {
            int t = __shfl_up_sync(0xFFFFFFFFu, v, off);
            if (lane >= off) v += t;
        }
        warpsum[lane] = v;
    }
    __syncthreads();
    int warpoff = (wrp > 0) ? warpsum[wrp - 1] : 0;
    int myoff = warpoff + incl - mysum;
#pragma unroll
    for (int k = 0; k < CH; k++) {
        int i = base + k;
        if (i < n) {
            g_rowptr[i] = myoff + loc[k];
            int deg = ((k + 1 < CH) ? loc[k + 1] : mysum) - loc[k];
            g_dinv[i] = rsqrtf((float)(deg + 1));
        }
    }
    if (tid == 1023) g_rowptr[n] = warpsum[31];
}

__global__ void scatter_kernel(const int* __restrict__ ei, int E) {
    int e = blockIdx.x * blockDim.x + threadIdx.x;
    if (e < E) {
        int d = ei[E + e];
        int pos = g_rowptr[d] + atomicAdd(&g_cursor[d], 1);
        g_col[pos] = ei[e];
    }
}

// ---------------- pipelined TF32 tensor-core GEMM ----------------
// C[M,Ncols] = A[M,K](lda) @ B[K,Ncols].
// A: fp32, tf32-rounded at fragment load. B: tf32-pre-rounded (raw load).
// EPI: 0 = raw store, 1 = bias + relu,
//      2 = raw store + per-head attention scalars (BN==128; head = blockIdx.x),
//      3 = EPI2 for bx < gridDim.x-1; last bx computes skip tile C2 = A@B2 (+bias2, relu).
template <int BM, int BN, int BK, int WM, int EPI>
__global__ __launch_bounds__((BM / WM) * (BN / 64) * 32)
void tf32gemm_pipe(const float* __restrict__ A, const float* __restrict__ B,
                   const float* __restrict__ bias, float* __restrict__ C,
                   int M, int K, int Ncols, int lda, int ldc,
                   const float* __restrict__ a_srcv, const float* __restrict__ a_dstv,
                   float* __restrict__ as_, float* __restrict__ ad_, int hstride,
                   const float* __restrict__ B2, const float* __restrict__ bias2,
                   float* __restrict__ C2)
{
    constexpr int NWY = BM / WM;
    constexpr int NWX = BN / 64;
    constexpr int THREADS = NWY * NWX * 32;
    constexpr int MF = WM / 16;
    constexpr int ASTR = BK + 4;
    constexpr int BSTR = BN + 8;
    constexpr int A_ITERS = BM * BK / 4 / THREADS;
    constexpr int B_ITERS = BK * BN / 4 / THREADS;

    extern __shared__ float smem[];
    float* As = smem;                       // [2][BM][ASTR]
    float* Bs = smem + 2 * BM * ASTR;       // [2][BK][BSTR]

    const int tid = threadIdx.x;
    const int wid = tid >> 5, lane = tid & 31;
    const int g = lane >> 2, tg = lane & 3;
    const int wm = (wid % NWY) * WM;
    const int wn = (wid / NWY) * 64;
    const int rowBase = blockIdx.y * BM;

    const bool isSkip = (EPI == 3) && (blockIdx.x == gridDim.x - 1);
    const float* Bp = isSkip ? B2 : B;
    const int ncols  = isSkip ? 64 : Ncols;
    const int colBase = isSkip ? 0 : blockIdx.x * BN;

    float acc[MF][8][4];
#pragma unroll
    for (int mf = 0; mf < MF; mf++)
#pragma unroll
        for (int nf = 0; nf < 8; nf++)
#pragma unroll
            for (int t = 0; t < 4; t++) acc[mf][nf][t] = 0.f;

    auto load_tiles = [&](int stage, int k0) {
        float* Asb = As + stage * BM * ASTR;
        float* Bsb = Bs + stage * BK * BSTR;
#pragma unroll
        for (int it = 0; it < A_ITERS; it++) {
            int id = tid + it * THREADS;
            int r = id / (BK / 4);
            int kq = id % (BK / 4);
            int grow = rowBase + r, gk = k0 + kq * 4;
            int sz = (grow < M && gk < K) ? 16 : 0;
            const float* src = A + (size_t)min(grow, M - 1) * lda + min(gk, K - 4);
            uint32_t dst = (uint32_t)__cvta_generic_to_shared(Asb + r * ASTR + kq * 4);
            asm volatile("cp.async.cg.shared.global [%0], [%1], 16, %2;"
                         :: "r"(dst), "l"(src), "r"(sz));
        }
#pragma unroll
        for (int it = 0; it < B_ITERS; it++) {
            int id = tid + it * THREADS;
            int kr = id / (BN / 4);
            int cq = id % (BN / 4);
            int gk = k0 + kr;
            int gcol = colBase + cq * 4;
            int sz = (gk < K && gcol + 3 < ncols) ? 16 : 0;
            const float* src = Bp + (size_t)min(gk, K - 1) * ncols + min(gcol, ncols - 4);
            uint32_t dst = (uint32_t)__cvta_generic_to_shared(Bsb + kr * BSTR + cq * 4);
            asm volatile("cp.async.cg.shared.global [%0], [%1], 16, %2;"
                         :: "r"(dst), "l"(src), "r"(sz));
        }
        asm volatile("cp.async.commit_group;");
    };

    const int iters = (K + BK - 1) / BK;
    load_tiles(0, 0);

    for (int it = 0; it < iters; it++) {
        if (it + 1 < iters) {
            load_tiles((it + 1) & 1, (it + 1) * BK);
            asm volatile("cp.async.wait_group 1;");
        } else {
            asm volatile("cp.async.wait_group 0;");
        }
        __syncthreads();

        const float* Asb = As + (it & 1) * BM * ASTR;
        const float* Bsb = Bs + (it & 1) * BK * BSTR;
#pragma unroll
        for (int ks = 0; ks < BK; ks += 8) {
            uint32_t a[MF][4], b[8][2];
#pragma unroll
            for (int mf = 0; mf < MF; mf++) {
                int rb = wm + mf * 16 + g;
                a[mf][0] = f2tf32(Asb[rb * ASTR + ks + tg]);
                a[mf][1] = f2tf32(Asb[(rb + 8) * ASTR + ks + tg]);
                a[mf][2] = f2tf32(Asb[rb * ASTR + ks + tg + 4]);
                a[mf][3] = f2tf32(Asb[(rb + 8) * ASTR + ks + tg + 4]);
            }
#pragma unroll
            for (int nf = 0; nf < 8; nf++) {
                int cb = wn + nf * 8 + g;
                b[nf][0] = __float_as_uint(Bsb[(ks + tg) * BSTR + cb]);
                b[nf][1] = __float_as_uint(Bsb[(ks + tg + 4) * BSTR + cb]);
            }
#pragma unroll
            for (int mf = 0; mf < MF; mf++)
#pragma unroll
                for (int nf = 0; nf < 8; nf++) {
                    asm volatile(
                        "mma.sync.aligned.m16n8k8.row.col.f32.tf32.tf32.f32 "
                        "{%0,%1,%2,%3}, {%4,%5,%6,%7}, {%8,%9}, {%0,%1,%2,%3};"
                        : "+f"(acc[mf][nf][0]), "+f"(acc[mf][nf][1]),
                          "+f"(acc[mf][nf][2]), "+f"(acc[mf][nf][3])
                        : "r"(a[mf][0]), "r"(a[mf][1]), "r"(a[mf][2]), "r"(a[mf][3]),
                          "r"(b[nf][0]), "r"(b[nf][1]));
                }
        }
        __syncthreads();
    }

    // ---- epilogues (branch uniform per CTA) ----
    if (isSkip) {
#pragma unroll
        for (int mf = 0; mf < MF; mf++) {
#pragma unroll
            for (int nf = 0; nf < 8; nf++) {
                int r0 = rowBase + wm + mf * 16 + g;
                int r1 = r0 + 8;
                int c = wn + nf * 8 + tg * 2;
                if (c + 1 >= 64) continue;
                float bz0 = bias2[c], bz1 = bias2[c + 1];
                float v0 = fmaxf(acc[mf][nf][0] + bz0, 0.f);
                float v1 = fmaxf(acc[mf][nf][1] + bz1, 0.f);
                float v2 = fmaxf(acc[mf][nf][2] + bz0, 0.f);
                float v3 = fmaxf(acc[mf][nf][3] + bz1, 0.f);
                if (r0 < M) *(float2*)(C2 + (size_t)r0 * 64 + c) = make_float2(v0, v1);
                if (r1 < M) *(float2*)(C2 + (size_t)r1 * 64 + c) = make_float2(v2, v3);
            }
        }
        return;
    }

#pragma unroll
    for (int mf = 0; mf < MF; mf++) {
#pragma unroll
        for (int nf = 0; nf < 8; nf++) {
            int r0 = rowBase + wm + mf * 16 + g;
            int r1 = r0 + 8;
            int c = colBase + wn + nf * 8 + tg * 2;
            float v0 = acc[mf][nf][0], v1 = acc[mf][nf][1];
            float v2 = acc[mf][nf][2], v3 = acc[mf][nf][3];
            if (EPI == 1) {
                float bz0 = bias[c], bz1 = bias[c + 1];
                v0 = fmaxf(v0 + bz0, 0.f); v1 = fmaxf(v1 + bz1, 0.f);
                v2 = fmaxf(v2 + bz0, 0.f); v3 = fmaxf(v3 + bz1, 0.f);
            }
            if (r0 < M) *(float2*)(C + (size_t)r0 * ldc + c) = make_float2(v0, v1);
            if (r1 < M) *(float2*)(C + (size_t)r1 * ldc + c) = make_float2(v2, v3);
        }
    }

    if (EPI == 2 || EPI == 3) {
        const int head = blockIdx.x;
        const float* av = a_srcv + head * 128;
        const float* dv = a_dstv + head * 128;
        float ps[MF][2], pd[MF][2];
#pragma unroll
        for (int mf = 0; mf < MF; mf++) { ps[mf][0] = ps[mf][1] = pd[mf][0] = pd[mf][1] = 0.f; }
#pragma unroll
        for (int nf = 0; nf < 8; nf++) {
            int c = wn + nf * 8 + tg * 2;
            float a0 = av[c], a1 = av[c + 1];
            float d0 = dv[c], d1 = dv[c + 1];
#pragma unroll
            for (int mf = 0; mf < MF; mf++) {
                ps[mf][0] += acc[mf][nf][0] * a0 + acc[mf][nf][1] * a1;
                ps[mf][1] += acc[mf][nf][2] * a0 + acc[mf][nf][3] * a1;
                pd[mf][0] += acc[mf][nf][0] * d0 + acc[mf][nf][1] * d1;
                pd[mf][1] += acc[mf][nf][2] * d0 + acc[mf][nf][3] * d1;
            }
        }
#pragma unroll
        for (int off = 1; off <= 2; off <<= 1) {
#pragma unroll
            for (int mf = 0; mf < MF; mf++) {
                ps[mf][0] += __shfl_xor_sync(0xFFFFFFFFu, ps[mf][0], off);
                ps[mf][1] += __shfl_xor_sync(0xFFFFFFFFu, ps[mf][1], off);
                pd[mf][0] += __shfl_xor_sync(0xFFFFFFFFu, pd[mf][0], off);
                pd[mf][1] += __shfl_xor_sync(0xFFFFFFFFu, pd[mf][1], off);
            }
        }
        float* sA = smem;   // [BM][2(sd)][2(colhalf)]
        for (int idx = tid; idx < BM * 4; idx += THREADS) sA[idx] = 0.f;
        __syncthreads();
        int ch = wn >> 6;
        if (tg == 0) {
#pragma unroll
            for (int mf = 0; mf < MF; mf++) {
                int r0 = wm + mf * 16 + g, r1 = r0 + 8;
                sA[r0 * 4 + 0 * 2 + ch] = ps[mf][0];
                sA[r1 * 4 + 0 * 2 + ch] = ps[mf][1];
                sA[r0 * 4 + 1 * 2 + ch] = pd[mf][0];
                sA[r1 * 4 + 1 * 2 + ch] = pd[mf][1];
            }
        }
        __syncthreads();
        for (int r = tid; r < BM; r += THREADS) {
            int grow = rowBase + r;
            if (grow < M) {
                as_[(size_t)grow * hstride + head] = sA[r * 4 + 0] + sA[r * 4 + 1];
                ad_[(size_t)grow * hstride + head] = sA[r * 4 + 2] + sA[r * 4 + 3];
            }
        }
    }
}

// ---------------- GAT aggregation: single-pass softmax ----------------
template <int H>
__global__ void gat_agg(const float* __restrict__ h, const float* __restrict__ as_,
                        const float* __restrict__ ad_, const float* __restrict__ bias,
                        const float* __restrict__ gamma, const float* __restrict__ beta,
                        float* __restrict__ out, int n)
{
    int lane = threadIdx.x & 31;
    int i = (blockIdx.x * blockDim.x + threadIdx.x) >> 5;
    if (i >= n) return;
    int s0 = g_rowptr[i], e0 = g_rowptr[i + 1];

    float adi[H], den[H];
    float4 acc4[H];
#pragma unroll
    for (int hh = 0; hh < H; hh++) adi[hh] = ad_[i * H + hh];
    {
        const float4* hr4 = (const float4*)(h + (size_t)i * (H * 128));
#pragma unroll
        for (int t = 0; t < H; t++) {
            float a = as_[i * H + t] + adi[t];
            a = a > 0.f ? a : 0.2f * a;
            float w = __expf(a);
            den[t] = w;
            float4 v = hr4[lane + 32 * t];
            acc4[t].x = w * v.x; acc4[t].y = w * v.y;
            acc4[t].z = w * v.z; acc4[t].w = w * v.w;
        }
    }
    for (int j = s0; j < e0; j++) {
        int src = g_col[j];
        float w[H];
#pragma unroll
        for (int hh = 0; hh < H; hh++) {
            float a = as_[src * H + hh] + adi[hh];
            a = a > 0.f ? a : 0.2f * a;
            w[hh] = __expf(a);
            den[hh] += w[hh];
        }
        const float4* hr4 = (const float4*)(h + (size_t)src * (H * 128));
#pragma unroll
        for (int t = 0; t < H; t++) {
            float4 v = hr4[lane + 32 * t];
            acc4[t].x += w[t] * v.x; acc4[t].y += w[t] * v.y;
            acc4[t].z += w[t] * v.z; acc4[t].w += w[t] * v.w;
        }
    }
    float4 vs = make_float4(0.f, 0.f, 0.f, 0.f);
#pragma unroll
    for (int t = 0; t < H; t++) {
        float r = 1.f / den[t];
        vs.x += acc4[t].x * r; vs.y += acc4[t].y * r;
        vs.z += acc4[t].z * r; vs.w += acc4[t].w * r;
    }
    const float invH = 1.f / H;
    float4 b4 = ((const float4*)bias)[lane];
    float4 v;
    v.x = vs.x * invH + b4.x; v.y = vs.y * invH + b4.y;
    v.z = vs.z * invH + b4.z; v.w = vs.w * invH + b4.w;
    float s = v.x + v.y + v.z + v.w;
    float sq = v.x * v.x + v.y * v.y + v.z * v.z + v.w * v.w;
    for (int off = 16; off; off >>= 1) {
        s += __shfl_xor_sync(0xFFFFFFFFu, s, off);
        sq += __shfl_xor_sync(0xFFFFFFFFu, sq, off);
    }
    float mu = s * (1.f / 128.f);
    float var = sq * (1.f / 128.f) - mu * mu;
    float rstd = rsqrtf(var + 1e-5f);
    float4 g4 = ((const float4*)gamma)[lane];
    float4 bt4 = ((const float4*)beta)[lane];
    float4 o;
    o.x = fmaxf((v.x - mu) * rstd * g4.x + bt4.x, 0.f);
    o.y = fmaxf((v.y - mu) * rstd * g4.y + bt4.y, 0.f);
    o.z = fmaxf((v.z - mu) * rstd * g4.z + bt4.z, 0.f);
    o.w = fmaxf((v.w - mu) * rstd * g4.w + bt4.w, 0.f);
    ((float4*)out)[(size_t)i * 32 + lane] = o;
}

// ---------------- GCN aggregation, C=128 (float4) ----------------
__global__ void gcn_agg128(const float* __restrict__ y, const float* __restrict__ bias,
                           float* __restrict__ out, int ldo, int coff, int n)
{
    int lane = threadIdx.x & 31;
    int i = (blockIdx.x * blockDim.x + threadIdx.x) >> 5;
    if (i >= n) return;
    int s0 = g_rowptr[i], e0 = g_rowptr[i + 1];
    float di = g_dinv[i];
    float4 acc = make_float4(0.f, 0.f, 0.f, 0.f);
    for (int j = s0; j < e0; j++) {
        int src = g_col[j];
        float cf = g_dinv[src] * di;
        float4 v = ((const float4*)(y + (size_t)src * 128))[lane];
        acc.x += cf * v.x; acc.y += cf * v.y; acc.z += cf * v.z; acc.w += cf * v.w;
    }
    {
        float cf = di * di;
        float4 v = ((const float4*)(y + (size_t)i * 128))[lane];
        acc.x += cf * v.x; acc.y += cf * v.y; acc.z += cf * v.z; acc.w += cf * v.w;
    }
    float4 b4 = ((const float4*)bias)[lane];
    float4 o;
    o.x = fmaxf(acc.x + b4.x, 0.f);
    o.y = fmaxf(acc.y + b4.y, 0.f);
    o.z = fmaxf(acc.z + b4.z, 0.f);
    o.w = fmaxf(acc.w + b4.w, 0.f);
    ((float4*)(out + (size_t)i * ldo + coff))[lane] = o;
}

// ---------------- GCN aggregation, C=64 (float2) ----------------
__global__ void gcn_agg64(const float* __restrict__ y, const float* __restrict__ bias,
                          float* __restrict__ out, int ldo, int coff, int n)
{
    int lane = threadIdx.x & 31;
    int i = (blockIdx.x * blockDim.x + threadIdx.x) >> 5;
    if (i >= n) return;
    int s0 = g_rowptr[i], e0 = g_rowptr[i + 1];
    float di = g_dinv[i];
    float2 acc = make_float2(0.f, 0.f);
    for (int j = s0; j < e0; j++) {
        int src = g_col[j];
        float cf = g_dinv[src] * di;
        float2 v = ((const float2*)(y + (size_t)src * 64))[lane];
        acc.x += cf * v.x; acc.y += cf * v.y;
    }
    {
        float cf = di * di;
        float2 v = ((const float2*)(y + (size_t)i * 64))[lane];
        acc.x += cf * v.x; acc.y += cf * v.y;
    }
    float2 b2 = ((const float2*)bias)[lane];
    float2 o;
    o.x = fmaxf(acc.x + b2.x, 0.f);
    o.y = fmaxf(acc.y + b2.y, 0.f);
    ((float2*)(out + (size_t)i * ldo + coff))[lane] = o;
}

// ---------------- final: LN(fused+skip) -> 64->32->16->5 MLP ----------------
__global__ void final_kernel(const float* __restrict__ fused, const float* __restrict__ skipb,
                             const float* __restrict__ g3, const float* __restrict__ be3,
                             const float* __restrict__ Wc1, const float* __restrict__ bc1,
                             const float* __restrict__ Wc2, const float* __restrict__ bc2,
                             const float* __restrict__ Wc3, const float* __restrict__ bc3,
                             float* __restrict__ out, int n)
{
    int lane = threadIdx.x & 31;
    int w = threadIdx.x >> 5;
    int i = blockIdx.x * 8 + w;
    __shared__ float fsh[8][64];
    __shared__ float h1sh[8][32];
    __shared__ float h2sh[8][16];
    if (i >= n) return;
    float v0 = fused[(size_t)i * 64 + lane] + skipb[(size_t)i * 64 + lane];
    float v1 = fused[(size_t)i * 64 + 32 + lane] + skipb[(size_t)i * 64 + 32 + lane];
    float s = v0 + v1, sq = v0 * v0 + v1 * v1;
    for (int off = 16; off; off >>= 1) {
        s += __shfl_xor_sync(0xFFFFFFFFu, s, off);
        sq += __shfl_xor_sync(0xFFFFFFFFu, sq, off);
    }
    float mu = s * (1.f / 64.f);
    float var = sq * (1.f / 64.f) - mu * mu;
    float rstd = rsqrtf(var + 1e-5f);
    fsh[w][lane]      = (v0 - mu) * rstd * g3[lane] + be3[lane];
    fsh[w][lane + 32] = (v1 - mu) * rstd * g3[lane + 32] + be3[lane + 32];
    __syncwarp();
    float a = bc1[lane];
#pragma unroll 8
    for (int c = 0; c < 64; c++) a += fsh[w][c] * Wc1[c * 32 + lane];
    h1sh[w][lane] = fmaxf(a, 0.f);
    __syncwarp();
    if (lane < 16) {
        float a2 = bc2[lane];
#pragma unroll 8
        for (int c = 0; c < 32; c++) a2 += h1sh[w][c] * Wc2[c * 16 + lane];
        h2sh[w][lane] = fmaxf(a2, 0.f);
    }
    __syncwarp();
    if (lane < 5) {
        float a3 = bc3[lane];
#pragma unroll
        for (int c = 0; c < 16; c++) a3 += h2sh[w][c] * Wc3[c * 5 + lane];
        out[(size_t)i * 5 + lane] = a3;
    }
}

// ---------------- launch ----------------
static void* symaddr(const void* sym) {
    void* p = nullptr;
    cudaGetSymbolAddress(&p, sym);
    return p;
}

extern "C" void kernel_launch(void* const* d_in, const int* in_sizes, int n_in,
                              void* d_out, int out_size)
{
    const float* x      = (const float*)d_in[0];
    const int*   ei     = (const int*)  d_in[1];
    const float* W_gat1 = (const float*)d_in[2];
    const float* a_src1 = (const float*)d_in[3];
    const float* a_dst1 = (const float*)d_in[4];
    const float* b_gat1 = (const float*)d_in[5];
    const float* W_gcn1 = (const float*)d_in[6];
    const float* b_gcn1 = (const float*)d_in[7];
    const float* W_gat2 = (const float*)d_in[8];
    const float* a_src2 = (const float*)d_in[9];
    const float* a_dst2 = (const float*)d_in[10];
    const float* b_gat2 = (const float*)d_in[11];
    const float* W_gcn2 = (const float*)d_in[12];
    const float* b_gcn2 = (const float*)d_in[13];
    const float* W_skip = (const float*)d_in[14];
    const float* b_skip = (const float*)d_in[15];
    const float* W_fuse = (const float*)d_in[16];
    const float* b_fuse = (const float*)d_in[17];
    const float* W_c1   = (const float*)d_in[18];
    const float* b_c1   = (const float*)d_in[19];
    const float* W_c2   = (const float*)d_in[20];
    const float* b_c2   = (const float*)d_in[21];
    const float* W_c3   = (const float*)d_in[22];
    const float* b_c3   = (const float*)d_in[23];
    const float* g1     = (const float*)d_in[24];
    const float* be1    = (const float*)d_in[25];
    const float* g2     = (const float*)d_in[26];
    const float* be2    = (const float*)d_in[27];
    const float* g3     = (const float*)d_in[28];
    const float* be3    = (const float*)d_in[29];

    const int N = in_sizes[0] / F_IN;       // 10000
    const int E = in_sizes[1] / 2;          // 160000

    float* p_wr    = (float*)symaddr(g_wr);
    float* p_h1    = (float*)symaddr(g_h1);
    float* p_as1   = (float*)symaddr(g_as1);
    float* p_ad1   = (float*)symaddr(g_ad1);
    float* p_x1gat = (float*)symaddr(g_x1gat);
    float* p_y1    = (float*)symaddr(g_y1);
    float* p_cat   = (float*)symaddr(g_cat);
    float* p_h2    = (float*)symaddr(g_h2);
    float* p_as2   = (float*)symaddr(g_as2);
    float* p_ad2   = (float*)symaddr(g_ad2);
    float* p_x2gat = (float*)symaddr(g_x2gat);
    float* p_y2    = (float*)symaddr(g_y2);
    float* p_skip  = (float*)symaddr(g_skip);
    float* p_fused = (float*)symaddr(g_fused);

    const int warpBlocks = (N * 32 + 255) / 256;
    const dim3 blk(256);
    const int rows128 = (N + 127) / 128;    // 79
    const int rows256 = (N + 255) / 256;    // 40
    const int rows64  = (N + 63) / 64;      // 157

    constexpr int SMEM_BIG256  = (2 * 256 * 36 + 2 * 32 * 136) * 4;  // 108544
    constexpr int SMEM_BIG     = (2 * 128 * 36 + 2 * 32 * 136) * 4;  // 71680
    constexpr int SMEM_M64N128 = (2 * 64 * 36 + 2 * 32 * 136) * 4;   // 53248
    constexpr int SMEM_M64N64  = (2 * 64 * 36 + 2 * 32 * 72) * 4;    // 36864

    cudaFuncSetAttribute((const void*)tf32gemm_pipe<256, 128, 32, 64, 3>,
                         cudaFuncAttributeMaxDynamicSharedMemorySize, SMEM_BIG256);
    cudaFuncSetAttribute((const void*)tf32gemm_pipe<128, 128, 32, 64, 2>,
                         cudaFuncAttributeMaxDynamicSharedMemorySize, SMEM_BIG);
    cudaFuncSetAttribute((const void*)tf32gemm_pipe<64, 128, 32, 32, 0>,
                         cudaFuncAttributeMaxDynamicSharedMemorySize, SMEM_M64N128);
    cudaFuncSetAttribute((const void*)tf32gemm_pipe<64, 64, 32, 32, 0>,
                         cudaFuncAttributeMaxDynamicSharedMemorySize, SMEM_M64N64);
    cudaFuncSetAttribute((const void*)tf32gemm_pipe<64, 64, 32, 32, 1>,
                         cudaFuncAttributeMaxDynamicSharedMemorySize, SMEM_M64N64);

    // weight pre-rounding (one launch; B-side raw loads in all GEMMs)
    {
        int maxn4 = 2000 * 768 / 4;
        round_weights_kernel<<<(maxn4 + 255) / 256, blk>>>(
            W_gat1, p_wr + WOFF_GAT1, 2000 * 768 / 4,
            W_gcn1, p_wr + WOFF_GCN1, 128 * 128 / 4,
            W_gat2, p_wr + WOFF_GAT2, 128 * 512 / 4,
            W_gcn2, p_wr + WOFF_GCN2, 128 * 64 / 4,
            W_skip, p_wr + WOFF_SKIP, 2000 * 64 / 4,
            W_fuse, p_wr + WOFF_FUSE, 192 * 64 / 4);
    }

    // graph build
    zero_kernel<<<(N + 255) / 256, blk>>>(N);
    deg_kernel<<<(E + 255) / 256, blk>>>(ei, E);
    scan_kernel<<<1, 1024>>>(N);
    scatter_kernel<<<(E + 255) / 256, blk>>>(ei, E);

    // GAT1 GEMM (BM=256) + fused attn scalars + fused skip GEMM (bx==6)
    tf32gemm_pipe<256, 128, 32, 64, 3><<<dim3(7, rows256), 256, SMEM_BIG256>>>(
        x, p_wr + WOFF_GAT1, nullptr, p_h1, N, F_IN, 768, F_IN, 768,
        a_src1, a_dst1, p_as1, p_ad1, 6,
        p_wr + WOFF_SKIP, b_skip, p_skip);
    gat_agg<6><<<warpBlocks, blk>>>(p_h1, p_as1, p_ad1, b_gat1, g1, be1, p_x1gat, N);

    // GCN1 -> cat[:, 0:128]  (BM=64)
    tf32gemm_pipe<64, 128, 32, 32, 0><<<dim3(1, rows64), 128, SMEM_M64N128>>>(
        p_x1gat, p_wr + WOFF_GCN1, nullptr, p_y1, N, 128, 128, 128, 128,
        nullptr, nullptr, nullptr, nullptr, 0, nullptr, nullptr, nullptr);
    gcn_agg128<<<warpBlocks, blk>>>(p_y1, b_gcn1, p_cat, 192, 0, N);

    // GAT2 GEMM + fused attn scalars
    tf32gemm_pipe<128, 128, 32, 64, 2><<<dim3(4, rows128), 128, SMEM_BIG>>>(
        p_cat, p_wr + WOFF_GAT2, nullptr, p_h2, N, 128, 512, 192, 512,
        a_src2, a_dst2, p_as2, p_ad2, 4, nullptr, nullptr, nullptr);
    gat_agg<4><<<warpBlocks, blk>>>(p_h2, p_as2, p_ad2, b_gat2, g2, be2, p_x2gat, N);

    // GCN2 -> cat[:, 128:192]  (BM=64)
    tf32gemm_pipe<64, 64, 32, 32, 0><<<dim3(1, rows64), 64, SMEM_M64N64>>>(
        p_x2gat, p_wr + WOFF_GCN2, nullptr, p_y2, N, 128, 64, 128, 64,
        nullptr, nullptr, nullptr, nullptr, 0, nullptr, nullptr, nullptr);
    gcn_agg64<<<warpBlocks, blk>>>(p_y2, b_gcn2, p_cat, 192, 128, N);

    // fuse  (BM=64)
    tf32gemm_pipe<64, 64, 32, 32, 1><<<dim3(1, rows64), 64, SMEM_M64N64>>>(
        p_cat, p_wr + WOFF_FUSE, b_fuse, p_fused, N, 192, 64, 192, 64,
        nullptr, nullptr, nullptr, nullptr, 0, nullptr, nullptr, nullptr);

    // final LN + classifier
    final_kernel<<<(N + 7) / 8, blk>>>(p_fused, p_skip, g3, be3,
                                       W_c1, b_c1, W_c2, b_c2, W_c3, b_c3,
                                       (float*)d_out, N);
}

// round 17
// speedup vs baseline: 1.0934x; 1.0934x over previous
#include <cuda_runtime.h>
#include <cuda_bf16.h>
#include <cstdint>

// ---------------- problem constants ----------------
#define NNODES 10000
#define NEDGES 160000
#define F_IN   2000
#define HID    128

// ---------------- device scratch (no cudaMalloc allowed) ----------------
__device__ float g_wr[2000 * 768 + 128 * 128 + 128 * 512 + 128 * 64 + 2000 * 64 + 192 * 64];
__device__ float g_h1[NNODES * 768];      // x @ W_gat1  [N,6,128]
__device__ float g_as1[NNODES * 6];
__device__ float g_ad1[NNODES * 6];
__device__ float g_x1gat[NNODES * 128];
__device__ float g_y1[NNODES * 128];      // x1_gat @ W_gcn1
__device__ float g_cat[NNODES * 192];     // [x1_gcn | x2_gcn]
__device__ float g_h2[NNODES * 512];      // x1_gcn @ W_gat2 [N,4,128]
__device__ float g_as2[NNODES * 4];
__device__ float g_ad2[NNODES * 4];
__device__ float g_x2gat[NNODES * 128];
__device__ float g_y2[NNODES * 64];       // x2_gat @ W_gcn2
__device__ float g_skip[NNODES * 64];
__device__ float g_fused[NNODES * 64];
__device__ int   g_deg[NNODES];
__device__ int   g_cursor[NNODES];
__device__ int   g_rowptr[NNODES + 1];
__device__ int   g_col[NEDGES];
__device__ float g_dinv[NNODES];

// weight offsets inside g_wr
#define WOFF_GAT1 0
#define WOFF_GCN1 (WOFF_GAT1 + 2000 * 768)
#define WOFF_GAT2 (WOFF_GCN1 + 128 * 128)
#define WOFF_GCN2 (WOFF_GAT2 + 128 * 512)
#define WOFF_SKIP (WOFF_GCN2 + 128 * 64)
#define WOFF_FUSE (WOFF_SKIP + 2000 * 64)

__device__ __forceinline__ uint32_t f2tf32(float x) {
    uint32_t r;
    asm("cvt.rna.tf32.f32 %0, %1;" : "=r"(r) : "f"(x));
    return r;
}
__device__ __forceinline__ float rnd_tf32f(float x) {
    return __uint_as_float(f2tf32(x));
}

// fused rounding of all six GEMM weights in one launch
__global__ void round_weights_kernel(
    const float* __restrict__ w0, float* __restrict__ o0, int n0,
    const float* __restrict__ w1, float* __restrict__ o1, int n1,
    const float* __restrict__ w2, float* __restrict__ o2, int n2,
    const float* __restrict__ w3, float* __restrict__ o3, int n3,
    const float* __restrict__ w4, float* __restrict__ o4, int n4,
    const float* __restrict__ w5, float* __restrict__ o5, int n5)
{
    int i = blockIdx.x * blockDim.x + threadIdx.x;
    auto doseg = [&](const float* w, float* o, int n) {
        if (i < n) {
            float4 v = ((const float4*)w)[i];
            v.x = rnd_tf32f(v.x); v.y = rnd_tf32f(v.y);
            v.z = rnd_tf32f(v.z); v.w = rnd_tf32f(v.w);
            ((float4*)o)[i] = v;
        }
    };
    doseg(w0, o0, n0); doseg(w1, o1, n1); doseg(w2, o2, n2);
    doseg(w3, o3, n3); doseg(w4, o4, n4); doseg(w5, o5, n5);
}

// ---------------- graph build ----------------
__global__ void deg_kernel(const int* __restrict__ ei, int E) {
    int e = blockIdx.x * blockDim.x + threadIdx.x;
    if (e < E) atomicAdd(&g_deg[ei[E + e]], 1);
}

// two-level warp-shuffle scan, vectorized int2 loads/stores
__global__ void scan_kernel(int n) {
    __shared__ int warpsum[32];
    const int tid = threadIdx.x;
    const int lane = tid & 31, wrp = tid >> 5;
    constexpr int CH = 10;
    const int base = tid * CH;

    int d[CH];
    if (base + CH <= n) {
#pragma unroll
        for (int q = 0; q < CH / 2; q++) {
            int2 v = *(const int2*)(g_deg + base + q * 2);
            d[q * 2] = v.x; d[q * 2 + 1] = v.y;
        }
    } else {
#pragma unroll
        for (int k = 0; k < CH; k++) d[k] = (base + k < n) ? g_deg[base + k] : 0;
    }
    int loc[CH];
    int mysum = 0;
#pragma unroll
    for (int k = 0; k < CH; k++) { loc[k] = mysum; mysum += d[k]; }

    int incl = mysum;
#pragma unroll
    for (int off = 1; off < 32; off <<= 1) {
        int t = __shfl_up_sync(0xFFFFFFFFu, incl, off);
        if (lane >= off) incl += t;
    }
    if (lane == 31) warpsum[wrp] = incl;
    __syncthreads();
    if (wrp == 0) {
        int v = warpsum[lane];
#pragma unroll
        for (int off = 1; off < 32; off <<= 1) {
            int t = __shfl_up_sync(0xFFFFFFFFu, v, off);
            if (lane >= off) v += t;
        }
        warpsum[lane] = v;
    }
    __syncthreads();
    int warpoff = (wrp > 0) ? warpsum[wrp - 1] : 0;
    int myoff = warpoff + incl - mysum;

    if (base + CH <= n) {
#pragma unroll
        for (int q = 0; q < CH / 2; q++) {
            int2 rp; rp.x = myoff + loc[q * 2]; rp.y = myoff + loc[q * 2 + 1];
            *(int2*)(g_rowptr + base + q * 2) = rp;
            float2 dv;
            dv.x = rsqrtf((float)(d[q * 2] + 1));
            dv.y = rsqrtf((float)(d[q * 2 + 1] + 1));
            *(float2*)(g_dinv + base + q * 2) = dv;
        }
    } else {
#pragma unroll
        for (int k = 0; k < CH; k++) {
            int i = base + k;
            if (i < n) {
                g_rowptr[i] = myoff + loc[k];
                g_dinv[i] = rsqrtf((float)(d[k] + 1));
            }
        }
    }
    if (tid == 1023) g_rowptr[n] = warpsum[31];
}

__global__ void scatter_kernel(const int* __restrict__ ei, int E) {
    int e = blockIdx.x * blockDim.x + threadIdx.x;
    if (e < E) {
        int dd = ei[E + e];
        int pos = g_rowptr[dd] + atomicAdd(&g_cursor[dd], 1);
        g_col[pos] = ei[e];
    }
}

// ---------------- pipelined TF32 tensor-core GEMM ----------------
// C[M,Ncols] = A[M,K](lda) @ B[K,Ncols].
// A: fp32, tf32-rounded at fragment load. B: tf32-pre-rounded (raw load).
// EPI: 0 = raw store, 1 = bias + relu,
//      2 = raw store + per-head attention scalars (BN==128; head = blockIdx.x),
//      3 = EPI2 for bx < gridDim.x-1; last bx computes skip tile C2 = A@B2 (+bias2, relu).
template <int BM, int BN, int BK, int WM, int EPI>
__global__ __launch_bounds__((BM / WM) * (BN / 64) * 32)
void tf32gemm_pipe(const float* __restrict__ A, const float* __restrict__ B,
                   const float* __restrict__ bias, float* __restrict__ C,
                   int M, int K, int Ncols, int lda, int ldc,
                   const float* __restrict__ a_srcv, const float* __restrict__ a_dstv,
                   float* __restrict__ as_, float* __restrict__ ad_, int hstride,
                   const float* __restrict__ B2, const float* __restrict__ bias2,
                   float* __restrict__ C2)
{
    constexpr int NWY = BM / WM;
    constexpr int NWX = BN / 64;
    constexpr int THREADS = NWY * NWX * 32;
    constexpr int MF = WM / 16;
    constexpr int ASTR = BK + 4;
    constexpr int BSTR = BN + 8;
    constexpr int A_ITERS = BM * BK / 4 / THREADS;
    constexpr int B_ITERS = BK * BN / 4 / THREADS;

    extern __shared__ float smem[];
    float* As = smem;                       // [2][BM][ASTR]
    float* Bs = smem + 2 * BM * ASTR;       // [2][BK][BSTR]

    const int tid = threadIdx.x;
    const int wid = tid >> 5, lane = tid & 31;
    const int g = lane >> 2, tg = lane & 3;
    const int wm = (wid % NWY) * WM;
    const int wn = (wid / NWY) * 64;
    const int rowBase = blockIdx.y * BM;

    const bool isSkip = (EPI == 3) && (blockIdx.x == gridDim.x - 1);
    const float* Bp = isSkip ? B2 : B;
    const int ncols  = isSkip ? 64 : Ncols;
    const int colBase = isSkip ? 0 : blockIdx.x * BN;

    float acc[MF][8][4];
#pragma unroll
    for (int mf = 0; mf < MF; mf++)
#pragma unroll
        for (int nf = 0; nf < 8; nf++)
#pragma unroll
            for (int t = 0; t < 4; t++) acc[mf][nf][t] = 0.f;

    auto load_tiles = [&](int stage, int k0) {
        float* Asb = As + stage * BM * ASTR;
        float* Bsb = Bs + stage * BK * BSTR;
#pragma unroll
        for (int it = 0; it < A_ITERS; it++) {
            int id = tid + it * THREADS;
            int r = id / (BK / 4);
            int kq = id % (BK / 4);
            int grow = rowBase + r, gk = k0 + kq * 4;
            int sz = (grow < M && gk < K) ? 16 : 0;
            const float* src = A + (size_t)min(grow, M - 1) * lda + min(gk, K - 4);
            uint32_t dst = (uint32_t)__cvta_generic_to_shared(Asb + r * ASTR + kq * 4);
            asm volatile("cp.async.cg.shared.global [%0], [%1], 16, %2;"
                         :: "r"(dst), "l"(src), "r"(sz));
        }
#pragma unroll
        for (int it = 0; it < B_ITERS; it++) {
            int id = tid + it * THREADS;
            int kr = id / (BN / 4);
            int cq = id % (BN / 4);
            int gk = k0 + kr;
            int gcol = colBase + cq * 4;
            int sz = (gk < K && gcol + 3 < ncols) ? 16 : 0;
            const float* src = Bp + (size_t)min(gk, K - 1) * ncols + min(gcol, ncols - 4);
            uint32_t dst = (uint32_t)__cvta_generic_to_shared(Bsb + kr * BSTR + cq * 4);
            asm volatile("cp.async.cg.shared.global [%0], [%1], 16, %2;"
                         :: "r"(dst), "l"(src), "r"(sz));
        }
        asm volatile("cp.async.commit_group;");
    };

    const int iters = (K + BK - 1) / BK;
    load_tiles(0, 0);

    for (int it = 0; it < iters; it++) {
        if (it + 1 < iters) {
            load_tiles((it + 1) & 1, (it + 1) * BK);
            asm volatile("cp.async.wait_group 1;");
        } else {
            asm volatile("cp.async.wait_group 0;");
        }
        __syncthreads();

        const float* Asb = As + (it & 1) * BM * ASTR;
        const float* Bsb = Bs + (it & 1) * BK * BSTR;
#pragma unroll
        for (int ks = 0; ks < BK; ks += 8) {
            uint32_t a[MF][4], b[8][2];
#pragma unroll
            for (int mf = 0; mf < MF; mf++) {
                int rb = wm + mf * 16 + g;
                a[mf][0] = f2tf32(Asb[rb * ASTR + ks + tg]);
                a[mf][1] = f2tf32(Asb[(rb + 8) * ASTR + ks + tg]);
                a[mf][2] = f2tf32(Asb[rb * ASTR + ks + tg + 4]);
                a[mf][3] = f2tf32(Asb[(rb + 8) * ASTR + ks + tg + 4]);
            }
#pragma unroll
            for (int nf = 0; nf < 8; nf++) {
                int cb = wn + nf * 8 + g;
                b[nf][0] = __float_as_uint(Bsb[(ks + tg) * BSTR + cb]);
                b[nf][1] = __float_as_uint(Bsb[(ks + tg + 4) * BSTR + cb]);
            }
#pragma unroll
            for (int mf = 0; mf < MF; mf++)
#pragma unroll
                for (int nf = 0; nf < 8; nf++) {
                    asm volatile(
                        "mma.sync.aligned.m16n8k8.row.col.f32.tf32.tf32.f32 "
                        "{%0,%1,%2,%3}, {%4,%5,%6,%7}, {%8,%9}, {%0,%1,%2,%3};"
                        : "+f"(acc[mf][nf][0]), "+f"(acc[mf][nf][1]),
                          "+f"(acc[mf][nf][2]), "+f"(acc[mf][nf][3])
                        : "r"(a[mf][0]), "r"(a[mf][1]), "r"(a[mf][2]), "r"(a[mf][3]),
                          "r"(b[nf][0]), "r"(b[nf][1]));
                }
        }
        __syncthreads();
    }

    // ---- epilogues (branch uniform per CTA) ----
    if (isSkip) {
#pragma unroll
        for (int mf = 0; mf < MF; mf++) {
#pragma unroll
            for (int nf = 0; nf < 8; nf++) {
                int r0 = rowBase + wm + mf * 16 + g;
                int r1 = r0 + 8;
                int c = wn + nf * 8 + tg * 2;
                if (c + 1 >= 64) continue;
                float bz0 = bias2[c], bz1 = bias2[c + 1];
                float v0 = fmaxf(acc[mf][nf][0] + bz0, 0.f);
                float v1 = fmaxf(acc[mf][nf][1] + bz1, 0.f);
                float v2 = fmaxf(acc[mf][nf][2] + bz0, 0.f);
                float v3 = fmaxf(acc[mf][nf][3] + bz1, 0.f);
                if (r0 < M) *(float2*)(C2 + (size_t)r0 * 64 + c) = make_float2(v0, v1);
                if (r1 < M) *(float2*)(C2 + (size_t)r1 * 64 + c) = make_float2(v2, v3);
            }
        }
        return;
    }

#pragma unroll
    for (int mf = 0; mf < MF; mf++) {
#pragma unroll
        for (int nf = 0; nf < 8; nf++) {
            int r0 = rowBase + wm + mf * 16 + g;
            int r1 = r0 + 8;
            int c = colBase + wn + nf * 8 + tg * 2;
            float v0 = acc[mf][nf][0], v1 = acc[mf][nf][1];
            float v2 = acc[mf][nf][2], v3 = acc[mf][nf][3];
            if (EPI == 1) {
                float bz0 = bias[c], bz1 = bias[c + 1];
                v0 = fmaxf(v0 + bz0, 0.f); v1 = fmaxf(v1 + bz1, 0.f);
                v2 = fmaxf(v2 + bz0, 0.f); v3 = fmaxf(v3 + bz1, 0.f);
            }
            if (r0 < M) *(float2*)(C + (size_t)r0 * ldc + c) = make_float2(v0, v1);
            if (r1 < M) *(float2*)(C + (size_t)r1 * ldc + c) = make_float2(v2, v3);
        }
    }

    if (EPI == 2 || EPI == 3) {
        const int head = blockIdx.x;
        const float* av = a_srcv + head * 128;
        const float* dv = a_dstv + head * 128;
        float ps[MF][2], pd[MF][2];
#pragma unroll
        for (int mf = 0; mf < MF; mf++) { ps[mf][0] = ps[mf][1] = pd[mf][0] = pd[mf][1] = 0.f; }
#pragma unroll
        for (int nf = 0; nf < 8; nf++) {
            int c = wn + nf * 8 + tg * 2;
            float a0 = av[c], a1 = av[c + 1];
            float d0 = dv[c], d1 = dv[c + 1];
#pragma unroll
            for (int mf = 0; mf < MF; mf++) {
                ps[mf][0] += acc[mf][nf][0] * a0 + acc[mf][nf][1] * a1;
                ps[mf][1] += acc[mf][nf][2] * a0 + acc[mf][nf][3] * a1;
                pd[mf][0] += acc[mf][nf][0] * d0 + acc[mf][nf][1] * d1;
                pd[mf][1] += acc[mf][nf][2] * d0 + acc[mf][nf][3] * d1;
            }
        }
#pragma unroll
        for (int off = 1; off <= 2; off <<= 1) {
#pragma unroll
            for (int mf = 0; mf < MF; mf++) {
                ps[mf][0] += __shfl_xor_sync(0xFFFFFFFFu, ps[mf][0], off);
                ps[mf][1] += __shfl_xor_sync(0xFFFFFFFFu, ps[mf][1], off);
                pd[mf][0] += __shfl_xor_sync(0xFFFFFFFFu, pd[mf][0], off);
                pd[mf][1] += __shfl_xor_sync(0xFFFFFFFFu, pd[mf][1], off);
            }
        }
        float* sA = smem;   // [BM][2(sd)][2(colhalf)]
        for (int idx = tid; idx < BM * 4; idx += THREADS) sA[idx] = 0.f;
        __syncthreads();
        int ch = wn >> 6;
        if (tg == 0) {
#pragma unroll
            for (int mf = 0; mf < MF; mf++) {
                int r0 = wm + mf * 16 + g, r1 = r0 + 8;
                sA[r0 * 4 + 0 * 2 + ch] = ps[mf][0];
                sA[r1 * 4 + 0 * 2 + ch] = ps[mf][1];
                sA[r0 * 4 + 1 * 2 + ch] = pd[mf][0];
                sA[r1 * 4 + 1 * 2 + ch] = pd[mf][1];
            }
        }
        __syncthreads();
        for (int r = tid; r < BM; r += THREADS) {
            int grow = rowBase + r;
            if (grow < M) {
                as_[(size_t)grow * hstride + head] = sA[r * 4 + 0] + sA[r * 4 + 1];
                ad_[(size_t)grow * hstride + head] = sA[r * 4 + 2] + sA[r * 4 + 3];
            }
        }
    }
}

// ---------------- GAT aggregation: single-pass softmax ----------------
template <int H>
__global__ void gat_agg(const float* __restrict__ h, const float* __restrict__ as_,
                        const float* __restrict__ ad_, const float* __restrict__ bias,
                        const float* __restrict__ gamma, const float* __restrict__ beta,
                        float* __restrict__ out, int n)
{
    int lane = threadIdx.x & 31;
    int i = (blockIdx.x * blockDim.x + threadIdx.x) >> 5;
    if (i >= n) return;
    int s0 = g_rowptr[i], e0 = g_rowptr[i + 1];

    float adi[H], den[H];
    float4 acc4[H];
#pragma unroll
    for (int hh = 0; hh < H; hh++) adi[hh] = ad_[i * H + hh];
    {
        const float4* hr4 = (const float4*)(h + (size_t)i * (H * 128));
#pragma unroll
        for (int t = 0; t < H; t++) {
            float a = as_[i * H + t] + adi[t];
            a = a > 0.f ? a : 0.2f * a;
            float w = __expf(a);
            den[t] = w;
            float4 v = hr4[lane + 32 * t];
            acc4[t].x = w * v.x; acc4[t].y = w * v.y;
            acc4[t].z = w * v.z; acc4[t].w = w * v.w;
        }
    }
    for (int j = s0; j < e0; j++) {
        int src = g_col[j];
        float w[H];
#pragma unroll
        for (int hh = 0; hh < H; hh++) {
            float a = as_[src * H + hh] + adi[hh];
            a = a > 0.f ? a : 0.2f * a;
            w[hh] = __expf(a);
            den[hh] += w[hh];
        }
        const float4* hr4 = (const float4*)(h + (size_t)src * (H * 128));
#pragma unroll
        for (int t = 0; t < H; t++) {
            float4 v = hr4[lane + 32 * t];
            acc4[t].x += w[t] * v.x; acc4[t].y += w[t] * v.y;
            acc4[t].z += w[t] * v.z; acc4[t].w += w[t] * v.w;
        }
    }
    float4 vs = make_float4(0.f, 0.f, 0.f, 0.f);
#pragma unroll
    for (int t = 0; t < H; t++) {
        float r = 1.f / den[t];
        vs.x += acc4[t].x * r; vs.y += acc4[t].y * r;
        vs.z += acc4[t].z * r; vs.w += acc4[t].w * r;
    }
    const float invH = 1.f / H;
    float4 b4 = ((const float4*)bias)[lane];
    float4 v;
    v.x = vs.x * invH + b4.x; v.y = vs.y * invH + b4.y;
    v.z = vs.z * invH + b4.z; v.w = vs.w * invH + b4.w;
    float s = v.x + v.y + v.z + v.w;
    float sq = v.x * v.x + v.y * v.y + v.z * v.z + v.w * v.w;
    for (int off = 16; off; off >>= 1) {
        s += __shfl_xor_sync(0xFFFFFFFFu, s, off);
        sq += __shfl_xor_sync(0xFFFFFFFFu, sq, off);
    }
    float mu = s * (1.f / 128.f);
    float var = sq * (1.f / 128.f) - mu * mu;
    float rstd = rsqrtf(var + 1e-5f);
    float4 g4 = ((const float4*)gamma)[lane];
    float4 bt4 = ((const float4*)beta)[lane];
    float4 o;
    o.x = fmaxf((v.x - mu) * rstd * g4.x + bt4.x, 0.f);
    o.y = fmaxf((v.y - mu) * rstd * g4.y + bt4.y, 0.f);
    o.z = fmaxf((v.z - mu) * rstd * g4.z + bt4.z, 0.f);
    o.w = fmaxf((v.w - mu) * rstd * g4.w + bt4.w, 0.f);
    ((float4*)out)[(size_t)i * 32 + lane] = o;
}

// ---------------- GCN aggregation, C=128 (float4) ----------------
__global__ void gcn_agg128(const float* __restrict__ y, const float* __restrict__ bias,
                           float* __restrict__ out, int ldo, int coff, int n)
{
    int lane = threadIdx.x & 31;
    int i = (blockIdx.x * blockDim.x + threadIdx.x) >> 5;
    if (i >= n) return;
    int s0 = g_rowptr[i], e0 = g_rowptr[i + 1];
    float di = g_dinv[i];
    float4 acc = make_float4(0.f, 0.f, 0.f, 0.f);
    for (int j = s0; j < e0; j++) {
        int src = g_col[j];
        float cf = g_dinv[src] * di;
        float4 v = ((const float4*)(y + (size_t)src * 128))[lane];
        acc.x += cf * v.x; acc.y += cf * v.y; acc.z += cf * v.z; acc.w += cf * v.w;
    }
    {
        float cf = di * di;
        float4 v = ((const float4*)(y + (size_t)i * 128))[lane];
        acc.x += cf * v.x; acc.y += cf * v.y; acc.z += cf * v.z; acc.w += cf * v.w;
    }
    float4 b4 = ((const float4*)bias)[lane];
    float4 o;
    o.x = fmaxf(acc.x + b4.x, 0.f);
    o.y = fmaxf(acc.y + b4.y, 0.f);
    o.z = fmaxf(acc.z + b4.z, 0.f);
    o.w = fmaxf(acc.w + b4.w, 0.f);
    ((float4*)(out + (size_t)i * ldo + coff))[lane] = o;
}

// ---------------- GCN aggregation, C=64 (float2) ----------------
__global__ void gcn_agg64(const float* __restrict__ y, const float* __restrict__ bias,
                          float* __restrict__ out, int ldo, int coff, int n)
{
    int lane = threadIdx.x & 31;
    int i = (blockIdx.x * blockDim.x + threadIdx.x) >> 5;
    if (i >= n) return;
    int s0 = g_rowptr[i], e0 = g_rowptr[i + 1];
    float di = g_dinv[i];
    float2 acc = make_float2(0.f, 0.f);
    for (int j = s0; j < e0; j++) {
        int src = g_col[j];
        float cf = g_dinv[src] * di;
        float2 v = ((const float2*)(y + (size_t)src * 64))[lane];
        acc.x += cf * v.x; acc.y += cf * v.y;
    }
    {
        float cf = di * di;
        float2 v = ((const float2*)(y + (size_t)i * 64))[lane];
        acc.x += cf * v.x; acc.y += cf * v.y;
    }
    float2 b2 = ((const float2*)bias)[lane];
    float2 o;
    o.x = fmaxf(acc.x + b2.x, 0.f);
    o.y = fmaxf(acc.y + b2.y, 0.f);
    ((float2*)(out + (size_t)i * ldo + coff))[lane] = o;
}

// ---------------- final: LN(fused+skip) -> 64->32->16->5 MLP ----------------
__global__ void final_kernel(const float* __restrict__ fused, const float* __restrict__ skipb,
                             const float* __restrict__ g3, const float* __restrict__ be3,
                             const float* __restrict__ Wc1, const float* __restrict__ bc1,
                             const float* __restrict__ Wc2, const float* __restrict__ bc2,
                             const float* __restrict__ Wc3, const float* __restrict__ bc3,
                             float* __restrict__ out, int n)
{
    int lane = threadIdx.x & 31;
    int w = threadIdx.x >> 5;
    int i = blockIdx.x * 8 + w;
    __shared__ float fsh[8][64];
    __shared__ float h1sh[8][32];
    __shared__ float h2sh[8][16];
    if (i >= n) return;
    float v0 = fused[(size_t)i * 64 + lane] + skipb[(size_t)i * 64 + lane];
    float v1 = fused[(size_t)i * 64 + 32 + lane] + skipb[(size_t)i * 64 + 32 + lane];
    float s = v0 + v1, sq = v0 * v0 + v1 * v1;
    for (int off = 16; off; off >>= 1) {
        s += __shfl_xor_sync(0xFFFFFFFFu, s, off);
        sq += __shfl_xor_sync(0xFFFFFFFFu, sq, off);
    }
    float mu = s * (1.f / 64.f);
    float var = sq * (1.f / 64.f) - mu * mu;
    float rstd = rsqrtf(var + 1e-5f);
    fsh[w][lane]      = (v0 - mu) * rstd * g3[lane] + be3[lane];
    fsh[w][lane + 32] = (v1 - mu) * rstd * g3[lane + 32] + be3[lane + 32];
    __syncwarp();
    float a = bc1[lane];
#pragma unroll 8
    for (int c = 0; c < 64; c++) a += fsh[w][c] * Wc1[c * 32 + lane];
    h1sh[w][lane] = fmaxf(a, 0.f);
    __syncwarp();
    if (lane < 16) {
        float a2 = bc2[lane];
#pragma unroll 8
        for (int c = 0; c < 32; c++) a2 += h1sh[w][c] * Wc2[c * 16 + lane];
        h2sh[w][lane] = fmaxf(a2, 0.f);
    }
    __syncwarp();
    if (lane < 5) {
        float a3 = bc3[lane];
#pragma unroll
        for (int c = 0; c < 16; c++) a3 += h2sh[w][c] * Wc3[c * 5 + lane];
        out[(size_t)i * 5 + lane] = a3;
    }
}

// ---------------- launch ----------------
static void* symaddr(const void* sym) {
    void* p = nullptr;
    cudaGetSymbolAddress(&p, sym);
    return p;
}

extern "C" void kernel_launch(void* const* d_in, const int* in_sizes, int n_in,
                              void* d_out, int out_size)
{
    const float* x      = (const float*)d_in[0];
    const int*   ei     = (const int*)  d_in[1];
    const float* W_gat1 = (const float*)d_in[2];
    const float* a_src1 = (const float*)d_in[3];
    const float* a_dst1 = (const float*)d_in[4];
    const float* b_gat1 = (const float*)d_in[5];
    const float* W_gcn1 = (const float*)d_in[6];
    const float* b_gcn1 = (const float*)d_in[7];
    const float* W_gat2 = (const float*)d_in[8];
    const float* a_src2 = (const float*)d_in[9];
    const float* a_dst2 = (const float*)d_in[10];
    const float* b_gat2 = (const float*)d_in[11];
    const float* W_gcn2 = (const float*)d_in[12];
    const float* b_gcn2 = (const float*)d_in[13];
    const float* W_skip = (const float*)d_in[14];
    const float* b_skip = (const float*)d_in[15];
    const float* W_fuse = (const float*)d_in[16];
    const float* b_fuse = (const float*)d_in[17];
    const float* W_c1   = (const float*)d_in[18];
    const float* b_c1   = (const float*)d_in[19];
    const float* W_c2   = (const float*)d_in[20];
    const float* b_c2   = (const float*)d_in[21];
    const float* W_c3   = (const float*)d_in[22];
    const float* b_c3   = (const float*)d_in[23];
    const float* g1     = (const float*)d_in[24];
    const float* be1    = (const float*)d_in[25];
    const float* g2     = (const float*)d_in[26];
    const float* be2    = (const float*)d_in[27];
    const float* g3     = (const float*)d_in[28];
    const float* be3    = (const float*)d_in[29];

    const int N = in_sizes[0] / F_IN;       // 10000
    const int E = in_sizes[1] / 2;          // 160000

    float* p_wr    = (float*)symaddr(g_wr);
    float* p_h1    = (float*)symaddr(g_h1);
    float* p_as1   = (float*)symaddr(g_as1);
    float* p_ad1   = (float*)symaddr(g_ad1);
    float* p_x1gat = (float*)symaddr(g_x1gat);
    float* p_y1    = (float*)symaddr(g_y1);
    float* p_cat   = (float*)symaddr(g_cat);
    float* p_h2    = (float*)symaddr(g_h2);
    float* p_as2   = (float*)symaddr(g_as2);
    float* p_ad2   = (float*)symaddr(g_ad2);
    float* p_x2gat = (float*)symaddr(g_x2gat);
    float* p_y2    = (float*)symaddr(g_y2);
    float* p_skip  = (float*)symaddr(g_skip);
    float* p_fused = (float*)symaddr(g_fused);
    int*   p_deg   = (int*)symaddr(g_deg);
    int*   p_cur   = (int*)symaddr(g_cursor);

    const int warpBlocks = (N * 32 + 255) / 256;
    const dim3 blk(256);
    const int rows128 = (N + 127) / 128;    // 79
    const int rows64  = (N + 63) / 64;      // 157

    constexpr int SMEM_BIG     = (2 * 128 * 36 + 2 * 32 * 136) * 4;  // 71680
    constexpr int SMEM_M64N128 = (2 * 64 * 36 + 2 * 32 * 136) * 4;   // 53248
    constexpr int SMEM_M64N64  = (2 * 64 * 36 + 2 * 32 * 72) * 4;    // 36864

    cudaFuncSetAttribute((const void*)tf32gemm_pipe<128, 128, 32, 64, 3>,
                         cudaFuncAttributeMaxDynamicSharedMemorySize, SMEM_BIG);
    cudaFuncSetAttribute((const void*)tf32gemm_pipe<128, 128, 32, 64, 2>,
                         cudaFuncAttributeMaxDynamicSharedMemorySize, SMEM_BIG);
    cudaFuncSetAttribute((const void*)tf32gemm_pipe<64, 128, 32, 32, 0>,
                         cudaFuncAttributeMaxDynamicSharedMemorySize, SMEM_M64N128);
    cudaFuncSetAttribute((const void*)tf32gemm_pipe<64, 64, 32, 32, 0>,
                         cudaFuncAttributeMaxDynamicSharedMemorySize, SMEM_M64N64);
    cudaFuncSetAttribute((const void*)tf32gemm_pipe<64, 64, 32, 32, 1>,
                         cudaFuncAttributeMaxDynamicSharedMemorySize, SMEM_M64N64);

    // weight pre-rounding (one launch; B-side raw loads in all GEMMs)
    {
        int maxn4 = 2000 * 768 / 4;
        round_weights_kernel<<<(maxn4 + 255) / 256, blk>>>(
            W_gat1, p_wr + WOFF_GAT1, 2000 * 768 / 4,
            W_gcn1, p_wr + WOFF_GCN1, 128 * 128 / 4,
            W_gat2, p_wr + WOFF_GAT2, 128 * 512 / 4,
            W_gcn2, p_wr + WOFF_GCN2, 128 * 64 / 4,
            W_skip, p_wr + WOFF_SKIP, 2000 * 64 / 4,
            W_fuse, p_wr + WOFF_FUSE, 192 * 64 / 4);
    }

    // graph build (deg/cursor zero via memset; capture-legal)
    cudaMemsetAsync(p_deg, 0, N * sizeof(int), 0);
    cudaMemsetAsync(p_cur, 0, N * sizeof(int), 0);
    deg_kernel<<<(E + 255) / 256, blk>>>(ei, E);
    scan_kernel<<<1, 1024>>>(N);
    scatter_kernel<<<(E + 255) / 256, blk>>>(ei, E);

    // GAT1 GEMM (BM=128) + fused attn scalars + fused skip GEMM (bx==6)
    tf32gemm_pipe<128, 128, 32, 64, 3><<<dim3(7, rows128), 128, SMEM_BIG>>>(
        x, p_wr + WOFF_GAT1, nullptr, p_h1, N, F_IN, 768, F_IN, 768,
        a_src1, a_dst1, p_as1, p_ad1, 6,
        p_wr + WOFF_SKIP, b_skip, p_skip);
    gat_agg<6><<<warpBlocks, blk>>>(p_h1, p_as1, p_ad1, b_gat1, g1, be1, p_x1gat, N);

    // GCN1 -> cat[:, 0:128]  (BM=64)
    tf32gemm_pipe<64, 128, 32, 32, 0><<<dim3(1, rows64), 128, SMEM_M64N128>>>(
        p_x1gat, p_wr + WOFF_GCN1, nullptr, p_y1, N, 128, 128, 128, 128,
        nullptr, nullptr, nullptr, nullptr, 0, nullptr, nullptr, nullptr);
    gcn_agg128<<<warpBlocks, blk>>>(p_y1, b_gcn1, p_cat, 192, 0, N);

    // GAT2 GEMM + fused attn scalars
    tf32gemm_pipe<128, 128, 32, 64, 2><<<dim3(4, rows128), 128, SMEM_BIG>>>(
        p_cat, p_wr + WOFF_GAT2, nullptr, p_h2, N, 128, 512, 192, 512,
        a_src2, a_dst2, p_as2, p_ad2, 4, nullptr, nullptr, nullptr);
    gat_agg<4><<<warpBlocks, blk>>>(p_h2, p_as2, p_ad2, b_gat2, g2, be2, p_x2gat, N);

    // GCN2 -> cat[:, 128:192]  (BM=64)
    tf32gemm_pipe<64, 64, 32, 32, 0><<<dim3(1, rows64), 64, SMEM_M64N64>>>(
        p_x2gat, p_wr + WOFF_GCN2, nullptr, p_y2, N, 128, 64, 128, 64,
        nullptr, nullptr, nullptr, nullptr, 0, nullptr, nullptr, nullptr);
    gcn_agg64<<<warpBlocks, blk>>>(p_y2, b_gcn2, p_cat, 192, 128, N);

    // fuse  (BM=64)
    tf32gemm_pipe<64, 64, 32, 32, 1><<<dim3(1, rows64), 64, SMEM_M64N64>>>(
        p_cat, p_wr + WOFF_FUSE, b_fuse, p_fused, N, 192, 64, 192, 64,
        nullptr, nullptr, nullptr, nullptr, 0, nullptr, nullptr, nullptr);

    // final LN + classifier
    final_kernel<<<(N + 7) / 8, blk>>>(p_fused, p_skip, g3, be3,
                                       W_c1, b_c1, W_c2, b_c2, W_c3, b_c3,
                                       (float*)d_out, N);
}